// round 4
// baseline (speedup 1.0000x reference)
#include <cuda_runtime.h>
#include <cuda_bf16.h>
#include <math.h>

typedef unsigned long long ull;

// Problem constants
#define BB 1
#define CC 32
#define HH 128
#define WW 160
#define DD 48
#define HW (HH*WW)          // 20480

// Padded per-(dz,dy) partial volumes U: (9, D+2, H+2, W+pad)
#define PD (DD+2)           // 50
#define PH (HH+2)           // 130
#define ROWS   164
#define SLICE  (PH*ROWS)    // 21320
#define CSTS   (PD*SLICE)   // 1,066,000 per volume

// Device globals zero-initialized at module load; halo cells of g_S are never
// written, so SAME-padding zeros in d/h are free and persistent.
__device__ float g_rot[2][9];
__device__ float g_trans[2][3];
__device__ float g_featT[3][HW*CC];          // (view, y, x, c) channel-last
__device__ float g_S[9u*CSTS];               // 9 padded partial volumes ~38MB
__device__ float g_cost[DD*HW];              // ~3.9 MB

#define FFMA2(d, a, b, c) \
    asm("fma.rn.f32x2 %0, %1, %2, %3;" : "=l"(d) : "l"(a), "l"(b), "l"(c))
#define PACK2(out, lo, hi) \
    asm("mov.b64 %0, {%1, %2};" : "=l"(out) : "f"(lo), "f"(hi))
#define UNPACK2(lo, hi, in) \
    asm("mov.b64 {%0, %1}, %2;" : "=f"(lo), "=f"(hi) : "l"(in))

// Dynamic smem layout (bytes). Total usage 93,344; allocate 120KB to force
// 1 block/SM (2x120KB > 228KB) leaving ~108KB L1 for gather locality.
#define OFF_WGT 0              // float4 [2 rows][2 views][160]
#define OFF_ADR 10240          // int4   [2][2][160]
#define OFF_VAR 20480          // float  [2 rows][160*36]
#define OFF_PWT 66560          // ull    [27*16]  (row k contiguous, 128B)
#define OFF_E0  70016          // float  [2 rows][9][162]
#define OFF_E2  81680          // float  [2 rows][9][162]
#define SMEM_BYTES (120*1024)

// ---------------------------------------------------------------------------
// Stage 0: proj_v @ inv(proj_ref) -> rot(3x3), trans(3) for views 1,2
// ---------------------------------------------------------------------------
__global__ void prep_kernel(const float* __restrict__ proj)
{
    if (threadIdx.x != 0 || blockIdx.x != 0) return;
    float A0[9], b0[3];
    for (int r = 0; r < 3; ++r) {
        for (int c = 0; c < 3; ++c) A0[r*3+c] = proj[r*4+c];
        b0[r] = proj[r*4+3];
    }
    float inv[9];
    inv[0] =  A0[4]*A0[8] - A0[5]*A0[7];
    inv[1] = -(A0[1]*A0[8] - A0[2]*A0[7]);
    inv[2] =  A0[1]*A0[5] - A0[2]*A0[4];
    inv[3] = -(A0[3]*A0[8] - A0[5]*A0[6]);
    inv[4] =  A0[0]*A0[8] - A0[2]*A0[6];
    inv[5] = -(A0[0]*A0[5] - A0[2]*A0[3]);
    inv[6] =  A0[3]*A0[7] - A0[4]*A0[6];
    inv[7] = -(A0[0]*A0[7] - A0[1]*A0[6]);
    inv[8] =  A0[0]*A0[4] - A0[1]*A0[3];
    float det = A0[0]*inv[0] + A0[1]*inv[3] + A0[2]*inv[6];
    float idet = 1.0f / det;
    for (int i = 0; i < 9; ++i) inv[i] *= idet;

    for (int v = 1; v < 3; ++v) {
        const float* P = proj + v*16;
        float Av[9], bv[3];
        for (int r = 0; r < 3; ++r) {
            for (int c = 0; c < 3; ++c) Av[r*3+c] = P[r*4+c];
            bv[r] = P[r*4+3];
        }
        float rot[9];
        for (int r = 0; r < 3; ++r)
            for (int c = 0; c < 3; ++c)
                rot[r*3+c] = Av[r*3+0]*inv[0*3+c] + Av[r*3+1]*inv[1*3+c] + Av[r*3+2]*inv[2*3+c];
        for (int r = 0; r < 3; ++r)
            g_trans[v-1][r] = bv[r] - (rot[r*3+0]*b0[0] + rot[r*3+1]*b0[1] + rot[r*3+2]*b0[2]);
        for (int i = 0; i < 9; ++i) g_rot[v-1][i] = rot[i];
    }
}

// ---------------------------------------------------------------------------
// Stage 1: tiled transpose (C,H,W) -> (H,W,C) for all 3 views.
// ---------------------------------------------------------------------------
__global__ void transpose_kernel(const float* __restrict__ f0,
                                 const float* __restrict__ f1,
                                 const float* __restrict__ f2)
{
    __shared__ float t[32][33];
    int v  = blockIdx.y;
    int p0 = blockIdx.x * 32;
    int tx = threadIdx.x, ty = threadIdx.y;
    const float* src = (v == 0) ? f0 : (v == 1) ? f1 : f2;

#pragma unroll
    for (int j = ty; j < 32; j += 8)
        t[j][tx] = src[j*HW + p0 + tx];
    __syncthreads();
#pragma unroll
    for (int j = ty; j < 32; j += 8)
        g_featT[v][(p0 + j)*CC + tx] = t[tx][j];
}

// ---------------------------------------------------------------------------
// Stage 2: warp + variance + fused channel GEMM + dx-fold.
// Block = (h, group of 8 depths), processed as 4 pairs of d-rows.
//  A: bilinear weights + addresses for 2 rows x 2 views x 160 w.
//  B: warp = 20 voxels, lane = channel -> coalesced 128B gathers (L1-resident
//     across the 8 depths); variance staged s_var[row][w][c].
//  D: thread = w: 27 dot products via FFMA2 for BOTH rows (weight broadcasts
//     amortized), dx-folded into 9 partial values U_{dz,dy} via smem edges,
//     stored into 9 padded volumes.
// ---------------------------------------------------------------------------
__global__ void __launch_bounds__(256)
warp_var_kernel(const float* __restrict__ depth_values,
                const float* __restrict__ w_reg)
{
    extern __shared__ char smraw[];
    float4* s_wgt = (float4*)(smraw + OFF_WGT);   // ((r*2+v)*160 + w)
    int4*   s_adr = (int4*)  (smraw + OFF_ADR);
    float*  s_var = (float*) (smraw + OFF_VAR);   // r*5760 + w*36 + c
    ull*    s_pwt = (ull*)   (smraw + OFF_PWT);   // k*16 + c2
    float*  s_e0  = (float*) (smraw + OFF_E0);    // (r*9 + k9)*162 + idx
    float*  s_e2  = (float*) (smraw + OFF_E2);

    int h      = blockIdx.x;
    int dgroup = blockIdx.y;
    int tid  = threadIdx.x;
    int lane = tid & 31;
    int warp = tid >> 5;

    // One-time: packed weights s_pwt[k*16+c2] = (wt[2c2][k], wt[2c2+1][k])
    for (int i = tid; i < 27*16; i += 256) {
        int k  = i >> 4;
        int c2 = i & 15;
        float lo = __ldg(w_reg + (2*c2    )*27 + k);
        float hi = __ldg(w_reg + (2*c2 + 1)*27 + k);
        ull p; PACK2(p, lo, hi);
        s_pwt[i] = p;
    }

    // Hoist ref-view features (d-independent): warp owns w = warp*20..+19
    float refv[20];
    {
        const float* f0p = g_featT[0] + (h*WW + warp*20)*CC + lane;
#pragma unroll
        for (int i = 0; i < 20; ++i) refv[i] = __ldg(f0p + i*CC);
    }

    const float* f1 = g_featT[1] + lane;
    const float* f2 = g_featT[2] + lane;

    for (int p = 0; p < 4; ++p) {
        int dbase = dgroup*8 + p*2;
        __syncthreads();   // protect smem from previous pair's readers

        // ---- Phase A: projection for 2 rows x 2 views x 160 w ----
        for (int t = tid; t < 640; t += 256) {
            int r   = t / 320;
            int rem = t - r*320;
            int v   = rem / 160;
            int w   = rem - v*160;
            float depth = __ldg(depth_values + dbase + r);
            float fx = (float)w, fy = (float)h;

            float px = (g_rot[v][0]*fx + g_rot[v][1]*fy + g_rot[v][2]) * depth + g_trans[v][0];
            float py = (g_rot[v][3]*fx + g_rot[v][4]*fy + g_rot[v][5]) * depth + g_trans[v][1];
            float pz = (g_rot[v][6]*fx + g_rot[v][7]*fy + g_rot[v][8]) * depth + g_trans[v][2];
            float gx = px / pz;
            float gy = py / pz;

            float x0f = floorf(gx), y0f = floorf(gy);
            float wx = gx - x0f, wy = gy - y0f;
            float x1f = x0f + 1.0f, y1f = y0f + 1.0f;

            float vx0 = (x0f >= 0.0f && x0f <= (float)(WW-1)) ? 1.0f : 0.0f;
            float vx1 = (x1f >= 0.0f && x1f <= (float)(WW-1)) ? 1.0f : 0.0f;
            float vy0 = (y0f >= 0.0f && y0f <= (float)(HH-1)) ? 1.0f : 0.0f;
            float vy1 = (y1f >= 0.0f && y1f <= (float)(HH-1)) ? 1.0f : 0.0f;

            float w00 = (1.0f-wx)*(1.0f-wy) * (vx0*vy0);
            float w10 = wx*(1.0f-wy)        * (vx1*vy0);
            float w01 = (1.0f-wx)*wy        * (vx0*vy1);
            float w11 = wx*wy               * (vx1*vy1);

            int x0 = (int)fminf(fmaxf(x0f, 0.0f), (float)(WW-1));
            int x1 = (int)fminf(fmaxf(x1f, 0.0f), (float)(WW-1));
            int y0 = (int)fminf(fmaxf(y0f, 0.0f), (float)(HH-1));
            int y1 = (int)fminf(fmaxf(y1f, 0.0f), (float)(HH-1));

            int si = (r*2 + v)*160 + w;
            s_wgt[si] = make_float4(w00, w10, w01, w11);
            s_adr[si] = make_int4((y0*WW + x0)*CC, (y0*WW + x1)*CC,
                                  (y1*WW + x0)*CC, (y1*WW + x1)*CC);
        }
        // zero fold-edge boundary cells: e0[.][0], e2[.][160]
        if (tid < 36) {
            int r  = tid / 18;
            int q  = tid - r*18;
            int a  = q / 9;
            int k9 = q - a*9;
            if (a) s_e2[(r*9 + k9)*162 + 160] = 0.0f;
            else   s_e0[(r*9 + k9)*162 + 0]   = 0.0f;
        }
        __syncthreads();

        // ---- Phase B: gathers + variance, both rows ----
#pragma unroll
        for (int r = 0; r < 2; ++r) {
            float* vr = s_var + r*5760;
            const float4* wgt = s_wgt + (r*2)*160;
            const int4*   adr = s_adr + (r*2)*160;
#pragma unroll 4
            for (int i = 0; i < 20; ++i) {
                int w = warp*20 + i;
                float ref = refv[i];
                float s = ref, q = ref*ref;
                {
                    float4 wt = wgt[w];
                    int4   ad = adr[w];
                    float f = wt.x*__ldg(f1 + ad.x) + wt.y*__ldg(f1 + ad.y)
                            + wt.z*__ldg(f1 + ad.z) + wt.w*__ldg(f1 + ad.w);
                    s += f; q += f*f;
                }
                {
                    float4 wt = wgt[160 + w];
                    int4   ad = adr[160 + w];
                    float f = wt.x*__ldg(f2 + ad.x) + wt.y*__ldg(f2 + ad.y)
                            + wt.z*__ldg(f2 + ad.z) + wt.w*__ldg(f2 + ad.w);
                    s += f; q += f*f;
                }
                const float inv3 = (1.0f/3.0f);
                float m = s * inv3;
                vr[w*36 + lane] = q * inv3 - m*m;
            }
        }
        __syncthreads();

        // ---- Phase D: dual-row channel GEMM + dx fold ----
        float S1a[9], S1b[9];
        if (tid < WW) {
            int w = tid;
            ull va[16], vb[16];
            const ull* qa = (const ull*)(s_var + w*36);
            const ull* qb = (const ull*)(s_var + 5760 + w*36);
#pragma unroll
            for (int j = 0; j < 16; ++j) { va[j] = qa[j]; vb[j] = qb[j]; }

#pragma unroll
            for (int k = 0; k < 27; ++k) {
                const ull* pw = s_pwt + k*16;
                ull aA = 0ull, aB = 0ull, bA = 0ull, bB = 0ull;
#pragma unroll
                for (int c2 = 0; c2 < 16; c2 += 2) {
                    ull w0 = pw[c2], w1 = pw[c2+1];
                    FFMA2(aA, va[c2],   w0, aA);
                    FFMA2(aB, va[c2+1], w1, aB);
                    FFMA2(bA, vb[c2],   w0, bA);
                    FFMA2(bB, vb[c2+1], w1, bB);
                }
                float x0, x1, y0, y1;
                UNPACK2(x0, x1, aA); UNPACK2(y0, y1, aB);
                float Sa = (x0 + x1) + (y0 + y1);
                UNPACK2(x0, x1, bA); UNPACK2(y0, y1, bB);
                float Sb = (x0 + x1) + (y0 + y1);

                int k9 = k / 3, dx = k - k9*3;
                if (dx == 0) {
                    s_e0[(0*9 + k9)*162 + w + 1] = Sa;
                    s_e0[(1*9 + k9)*162 + w + 1] = Sb;
                } else if (dx == 1) {
                    S1a[k9] = Sa; S1b[k9] = Sb;
                } else {
                    s_e2[(0*9 + k9)*162 + w] = Sa;
                    s_e2[(1*9 + k9)*162 + w] = Sb;
                }
            }
        }
        __syncthreads();

        if (tid < WW) {
            int w = tid;
            size_t base = (size_t)(dbase + 1)*SLICE + (h + 1)*ROWS + (w + 1);
#pragma unroll
            for (int k9 = 0; k9 < 9; ++k9) {
                float Ua = s_e0[(0*9 + k9)*162 + w] + S1a[k9] + s_e2[(0*9 + k9)*162 + w + 1];
                float Ub = s_e0[(1*9 + k9)*162 + w] + S1b[k9] + s_e2[(1*9 + k9)*162 + w + 1];
                g_S[(size_t)k9*CSTS + base]         = Ua;
                g_S[(size_t)k9*CSTS + base + SLICE] = Ub;
            }
        }
    }
}

// ---------------------------------------------------------------------------
// Stage 3: 9-tap shifted-sum of partial volumes -> cost.
// cost(d,h,w) = sum_{dz,dy} U_{dz,dy}(padded d+dz, h+dy, w+1)
// ---------------------------------------------------------------------------
__global__ void __launch_bounds__(256)
sum_kernel()
{
    int idx = blockIdx.x * 256 + threadIdx.x;      // DD*HH*WW = 983040
    int w = idx % WW;
    int t = idx / WW;
    int h = t % HH;
    int d = t / HH;

    const float* base = g_S + (size_t)d*SLICE + h*ROWS + (w + 1);
    float acc = 0.0f;
#pragma unroll
    for (int k9 = 0; k9 < 9; ++k9) {
        int dz = k9 / 3, dy = k9 - dz*3;
        acc += __ldg(base + (size_t)k9*CSTS + dz*SLICE + dy*ROWS);
    }
    g_cost[d*HW + h*WW + w] = acc;
}

// ---------------------------------------------------------------------------
// Stage 4: softmax over D, expected depth + max-prob confidence.
// b_reg shifts all logits equally -> cancels in softmax -> ignored.
// ---------------------------------------------------------------------------
__global__ void __launch_bounds__(128)
depth_kernel(const float* __restrict__ depth_values, float* __restrict__ out)
{
    int pix = blockIdx.x * 128 + threadIdx.x;
    if (pix >= HW) return;

    float cv[DD];
    float m = -1e30f;
#pragma unroll
    for (int d = 0; d < DD; ++d) {
        cv[d] = g_cost[d*HW + pix];
        m = fmaxf(m, cv[d]);
    }
    float sum = 0.0f, dep = 0.0f, best = 0.0f;
#pragma unroll
    for (int d = 0; d < DD; ++d) {
        float e = expf(cv[d] - m);
        sum += e;
        dep += e * __ldg(depth_values + d);
        best = fmaxf(best, e);
    }
    float isum = 1.0f / sum;
    out[pix]      = dep * isum;
    out[HW + pix] = best * isum;
}

// ---------------------------------------------------------------------------
extern "C" void kernel_launch(void* const* d_in, const int* in_sizes, int n_in,
                              void* d_out, int out_size)
{
    const float* feat0 = (const float*)d_in[0];
    const float* feat1 = (const float*)d_in[1];
    const float* feat2 = (const float*)d_in[2];
    const float* proj  = (const float*)d_in[3];
    const float* dvals = (const float*)d_in[4];
    const float* wreg  = (const float*)d_in[5];
    float* out = (float*)d_out;

    cudaFuncSetAttribute(warp_var_kernel,
                         cudaFuncAttributeMaxDynamicSharedMemorySize, SMEM_BYTES);

    prep_kernel<<<1, 1>>>(proj);
    transpose_kernel<<<dim3(HW/32, 3), dim3(32, 8)>>>(feat0, feat1, feat2);
    warp_var_kernel<<<dim3(HH, DD/8), 256, SMEM_BYTES>>>(dvals, wreg);
    sum_kernel<<<(DD*HH*WW)/256, 256>>>();
    depth_kernel<<<(HW + 127)/128, 128>>>(dvals, out);
}

// round 5
// speedup vs baseline: 1.7018x; 1.7018x over previous
#include <cuda_runtime.h>
#include <cuda_bf16.h>
#include <math.h>

typedef unsigned long long ull;

// Problem constants
#define BB 1
#define CC 32
#define HH 128
#define WW 160
#define DD 48
#define HW (HH*WW)          // 20480

// Padded per-(dz,dy) partial volumes U: (9, D+2, H+2, W+pad)
#define PD (DD+2)           // 50
#define PH (HH+2)           // 130
#define ROWS   164
#define SLICE  (PH*ROWS)    // 21320
#define CSTS   (PD*SLICE)   // 1,066,000 per volume

// Device globals zero-initialized at module load; halo cells of g_S are never
// written, so SAME-padding zeros in d/h are free and persistent.
__device__ float g_rot[2][9];
__device__ float g_trans[2][3];
__device__ float g_featT[3][HW*CC];          // (view, y, x, c) channel-last
__device__ float g_S[9u*CSTS];               // 9 padded partial volumes ~38MB
__device__ float g_cost[DD*HW];              // ~3.9 MB

#define FFMA2(d, a, b, c) \
    asm("fma.rn.f32x2 %0, %1, %2, %3;" : "=l"(d) : "l"(a), "l"(b), "l"(c))
#define PACK2(out, lo, hi) \
    asm("mov.b64 %0, {%1, %2};" : "=l"(out) : "f"(lo), "f"(hi))
#define UNPACK2(lo, hi, in) \
    asm("mov.b64 {%0, %1}, %2;" : "=f"(lo), "=f"(hi) : "l"(in))

// Dynamic smem layout (floats/bytes)
// s_wgt : float4 [2][160]       5120 B   @ 0
// s_adr : int4   [2][160]       5120 B   @ 5120
// s_var : float  [160][40]     25600 B   @ 10240   (stride 40 -> 16B aligned)
// s_pwt : ull    [27*16]        3456 B   @ 35840
// s_e0  : float  [9][162]       5832 B   @ 39296
// s_e2  : float  [9][162]       5832 B   @ 45128
#define OFF_WGT 0
#define OFF_ADR 5120
#define OFF_VAR 10240
#define OFF_PWT 35840
#define OFF_E0  39296
#define OFF_E2  45128
#define SMEM_BYTES 50960

// ---------------------------------------------------------------------------
// Stage 0: proj_v @ inv(proj_ref) -> rot(3x3), trans(3) for views 1,2
// ---------------------------------------------------------------------------
__global__ void prep_kernel(const float* __restrict__ proj)
{
    if (threadIdx.x != 0 || blockIdx.x != 0) return;
    float A0[9], b0[3];
    for (int r = 0; r < 3; ++r) {
        for (int c = 0; c < 3; ++c) A0[r*3+c] = proj[r*4+c];
        b0[r] = proj[r*4+3];
    }
    float inv[9];
    inv[0] =  A0[4]*A0[8] - A0[5]*A0[7];
    inv[1] = -(A0[1]*A0[8] - A0[2]*A0[7]);
    inv[2] =  A0[1]*A0[5] - A0[2]*A0[4];
    inv[3] = -(A0[3]*A0[8] - A0[5]*A0[6]);
    inv[4] =  A0[0]*A0[8] - A0[2]*A0[6];
    inv[5] = -(A0[0]*A0[5] - A0[2]*A0[3]);
    inv[6] =  A0[3]*A0[7] - A0[4]*A0[6];
    inv[7] = -(A0[0]*A0[7] - A0[1]*A0[6]);
    inv[8] =  A0[0]*A0[4] - A0[1]*A0[3];
    float det = A0[0]*inv[0] + A0[1]*inv[3] + A0[2]*inv[6];
    float idet = 1.0f / det;
    for (int i = 0; i < 9; ++i) inv[i] *= idet;

    for (int v = 1; v < 3; ++v) {
        const float* P = proj + v*16;
        float Av[9], bv[3];
        for (int r = 0; r < 3; ++r) {
            for (int c = 0; c < 3; ++c) Av[r*3+c] = P[r*4+c];
            bv[r] = P[r*4+3];
        }
        float rot[9];
        for (int r = 0; r < 3; ++r)
            for (int c = 0; c < 3; ++c)
                rot[r*3+c] = Av[r*3+0]*inv[0*3+c] + Av[r*3+1]*inv[1*3+c] + Av[r*3+2]*inv[2*3+c];
        for (int r = 0; r < 3; ++r)
            g_trans[v-1][r] = bv[r] - (rot[r*3+0]*b0[0] + rot[r*3+1]*b0[1] + rot[r*3+2]*b0[2]);
        for (int i = 0; i < 9; ++i) g_rot[v-1][i] = rot[i];
    }
}

// ---------------------------------------------------------------------------
// Stage 1: tiled transpose (C,H,W) -> (H,W,C) for all 3 views.
// ---------------------------------------------------------------------------
__global__ void transpose_kernel(const float* __restrict__ f0,
                                 const float* __restrict__ f1,
                                 const float* __restrict__ f2)
{
    __shared__ float t[32][33];
    int v  = blockIdx.y;
    int p0 = blockIdx.x * 32;
    int tx = threadIdx.x, ty = threadIdx.y;
    const float* src = (v == 0) ? f0 : (v == 1) ? f1 : f2;

#pragma unroll
    for (int j = ty; j < 32; j += 8)
        t[j][tx] = src[j*HW + p0 + tx];
    __syncthreads();
#pragma unroll
    for (int j = ty; j < 32; j += 8)
        g_featT[v][(p0 + j)*CC + tx] = t[tx][j];
}

// ---------------------------------------------------------------------------
// Stage 2: warp + variance + fused channel GEMM + dx-fold.
// Block per (d,h), 256 threads, ~51KB smem -> 4 blocks/SM.
//  A: bilinear weights + pixel addresses (2 views x 160 w) + packed weights.
//  B: half-warp = voxel, lane = channel PAIR (float2): every corner load is
//     one LDG.64 serving two voxels (4.5 LDG/voxel).  Variance -> s_var[w][c].
//  D: thread = w: 27 FFMA2 dot products over 32 channels, dx-folded into 9
//     partial values U_{dz,dy} via smem edge rows; 9 stores per voxel.
// ---------------------------------------------------------------------------
__global__ void __launch_bounds__(256)
warp_var_kernel(const float* __restrict__ depth_values,
                const float* __restrict__ w_reg)
{
    extern __shared__ char smraw[];
    float4* s_wgt = (float4*)(smraw + OFF_WGT);   // [v*160 + w]
    int4*   s_adr = (int4*)  (smraw + OFF_ADR);   // pixel*16 (float2 index)
    float*  s_var = (float*) (smraw + OFF_VAR);   // w*40 + c
    ull*    s_pwt = (ull*)   (smraw + OFF_PWT);   // k*16 + c2
    float*  s_e0  = (float*) (smraw + OFF_E0);    // k9*162 + idx
    float*  s_e2  = (float*) (smraw + OFF_E2);

    int blk = blockIdx.x;                  // 0 .. DD*HH-1
    int d = blk / HH;
    int h = blk - d*HH;
    int tid = threadIdx.x;

    float depth = __ldg(depth_values + d);

    // ---- Phase A: projection coords per (view, w) ----
    for (int t = tid; t < 2*WW; t += 256) {
        int v = t / WW;
        int w = t - v*WW;
        float fx = (float)w, fy = (float)h;

        float px = (g_rot[v][0]*fx + g_rot[v][1]*fy + g_rot[v][2]) * depth + g_trans[v][0];
        float py = (g_rot[v][3]*fx + g_rot[v][4]*fy + g_rot[v][5]) * depth + g_trans[v][1];
        float pz = (g_rot[v][6]*fx + g_rot[v][7]*fy + g_rot[v][8]) * depth + g_trans[v][2];
        float gx = px / pz;
        float gy = py / pz;

        float x0f = floorf(gx), y0f = floorf(gy);
        float wx = gx - x0f, wy = gy - y0f;
        float x1f = x0f + 1.0f, y1f = y0f + 1.0f;

        float vx0 = (x0f >= 0.0f && x0f <= (float)(WW-1)) ? 1.0f : 0.0f;
        float vx1 = (x1f >= 0.0f && x1f <= (float)(WW-1)) ? 1.0f : 0.0f;
        float vy0 = (y0f >= 0.0f && y0f <= (float)(HH-1)) ? 1.0f : 0.0f;
        float vy1 = (y1f >= 0.0f && y1f <= (float)(HH-1)) ? 1.0f : 0.0f;

        float w00 = (1.0f-wx)*(1.0f-wy) * (vx0*vy0);
        float w10 = wx*(1.0f-wy)        * (vx1*vy0);
        float w01 = (1.0f-wx)*wy        * (vx0*vy1);
        float w11 = wx*wy               * (vx1*vy1);

        int x0 = (int)fminf(fmaxf(x0f, 0.0f), (float)(WW-1));
        int x1 = (int)fminf(fmaxf(x1f, 0.0f), (float)(WW-1));
        int y0 = (int)fminf(fmaxf(y0f, 0.0f), (float)(HH-1));
        int y1 = (int)fminf(fmaxf(y1f, 0.0f), (float)(HH-1));

        s_wgt[t] = make_float4(w00, w10, w01, w11);
        s_adr[t] = make_int4((y0*WW + x0)*16, (y0*WW + x1)*16,
                             (y1*WW + x0)*16, (y1*WW + x1)*16);
    }

    // Packed weights: s_pwt[k*16+c2] = (wt[2c2][k], wt[2c2+1][k])
    for (int i = tid; i < 27*16; i += 256) {
        int k  = i >> 4;
        int c2 = i & 15;
        float lo = __ldg(w_reg + (2*c2    )*27 + k);
        float hi = __ldg(w_reg + (2*c2 + 1)*27 + k);
        ull p; PACK2(p, lo, hi);
        s_pwt[i] = p;
    }
    // zero fold-edge boundary cells (written once per block)
    if (tid < 18) {
        int a  = tid / 9;
        int k9 = tid - a*9;
        if (a) s_e2[k9*162 + 160] = 0.0f;
        else   s_e0[k9*162 + 0]   = 0.0f;
    }
    __syncthreads();

    // ---- Phase B: paired-voxel float2 gathers + variance ----
    {
        int lane = tid & 31;
        int warp = tid >> 5;
        int half = lane >> 4;          // which voxel of the pair
        int c2   = lane & 15;          // channel pair index

        const float2* F0 = (const float2*)g_featT[0];
        const float2* F1 = (const float2*)g_featT[1];
        const float2* F2 = (const float2*)g_featT[2];

#pragma unroll 5
        for (int i = 0; i < 10; ++i) {
            int w = warp*20 + 2*i + half;

            float2 ref = __ldg(F0 + (h*WW + w)*16 + c2);
            float sx = ref.x, sy = ref.y;
            float qx = ref.x*ref.x, qy = ref.y*ref.y;

            {
                float4 wt = s_wgt[w];
                int4   ad = s_adr[w];
                float2 a = __ldg(F1 + ad.x + c2);
                float2 b = __ldg(F1 + ad.y + c2);
                float2 c = __ldg(F1 + ad.z + c2);
                float2 e = __ldg(F1 + ad.w + c2);
                float fxv = wt.x*a.x + wt.y*b.x + wt.z*c.x + wt.w*e.x;
                float fyv = wt.x*a.y + wt.y*b.y + wt.z*c.y + wt.w*e.y;
                sx += fxv; qx += fxv*fxv;
                sy += fyv; qy += fyv*fyv;
            }
            {
                float4 wt = s_wgt[160 + w];
                int4   ad = s_adr[160 + w];
                float2 a = __ldg(F2 + ad.x + c2);
                float2 b = __ldg(F2 + ad.y + c2);
                float2 c = __ldg(F2 + ad.z + c2);
                float2 e = __ldg(F2 + ad.w + c2);
                float fxv = wt.x*a.x + wt.y*b.x + wt.z*c.x + wt.w*e.x;
                float fyv = wt.x*a.y + wt.y*b.y + wt.z*c.y + wt.w*e.y;
                sx += fxv; qx += fxv*fxv;
                sy += fyv; qy += fyv*fyv;
            }

            const float inv3 = (1.0f/3.0f);
            float mx = sx * inv3, my = sy * inv3;
            float2 var = make_float2(qx*inv3 - mx*mx, qy*inv3 - my*my);
            *(float2*)(s_var + w*40 + 2*c2) = var;
        }
    }
    __syncthreads();

    // ---- Phase D: channel GEMM (FFMA2) + dx fold ----
    float S1[9];
    if (tid < WW) {
        int w = tid;
        ull va[16];
        const ulonglong2* qv = (const ulonglong2*)(s_var + w*40);
#pragma unroll
        for (int j = 0; j < 8; ++j) {
            ulonglong2 p = qv[j];
            va[2*j] = p.x; va[2*j+1] = p.y;
        }

#pragma unroll
        for (int k = 0; k < 27; ++k) {
            const ulonglong2* pw = (const ulonglong2*)(s_pwt + k*16);
            ull accA = 0ull, accB = 0ull;
#pragma unroll
            for (int c2 = 0; c2 < 8; ++c2) {
                ulonglong2 wp = pw[c2];
                FFMA2(accA, va[2*c2],   wp.x, accA);
                FFMA2(accB, va[2*c2+1], wp.y, accB);
            }
            float x0, x1, y0, y1;
            UNPACK2(x0, x1, accA);
            UNPACK2(y0, y1, accB);
            float S = (x0 + x1) + (y0 + y1);

            int k9 = k / 3, dx = k - k9*3;
            if (dx == 0)      s_e0[k9*162 + w + 1] = S;
            else if (dx == 1) S1[k9] = S;
            else              s_e2[k9*162 + w] = S;
        }
    }
    __syncthreads();

    if (tid < WW) {
        int w = tid;
        size_t base = (size_t)(d + 1)*SLICE + (h + 1)*ROWS + (w + 1);
#pragma unroll
        for (int k9 = 0; k9 < 9; ++k9) {
            float U = s_e0[k9*162 + w] + S1[k9] + s_e2[k9*162 + w + 1];
            g_S[(size_t)k9*CSTS + base] = U;
        }
    }
}

// ---------------------------------------------------------------------------
// Stage 3: 9-tap shifted-sum of partial volumes -> cost.
// ---------------------------------------------------------------------------
__global__ void __launch_bounds__(256)
sum_kernel()
{
    int idx = blockIdx.x * 256 + threadIdx.x;      // DD*HH*WW = 983040
    int w = idx % WW;
    int t = idx / WW;
    int h = t % HH;
    int d = t / HH;

    const float* base = g_S + (size_t)d*SLICE + h*ROWS + (w + 1);
    float acc = 0.0f;
#pragma unroll
    for (int k9 = 0; k9 < 9; ++k9) {
        int dz = k9 / 3, dy = k9 - dz*3;
        acc += __ldg(base + (size_t)k9*CSTS + dz*SLICE + dy*ROWS);
    }
    g_cost[d*HW + h*WW + w] = acc;
}

// ---------------------------------------------------------------------------
// Stage 4: softmax over D, expected depth + max-prob confidence.
// b_reg shifts all logits equally -> cancels in softmax -> ignored.
// ---------------------------------------------------------------------------
__global__ void __launch_bounds__(128)
depth_kernel(const float* __restrict__ depth_values, float* __restrict__ out)
{
    int pix = blockIdx.x * 128 + threadIdx.x;
    if (pix >= HW) return;

    float cv[DD];
    float m = -1e30f;
#pragma unroll
    for (int d = 0; d < DD; ++d) {
        cv[d] = g_cost[d*HW + pix];
        m = fmaxf(m, cv[d]);
    }
    float sum = 0.0f, dep = 0.0f, best = 0.0f;
#pragma unroll
    for (int d = 0; d < DD; ++d) {
        float e = expf(cv[d] - m);
        sum += e;
        dep += e * __ldg(depth_values + d);
        best = fmaxf(best, e);
    }
    float isum = 1.0f / sum;
    out[pix]      = dep * isum;
    out[HW + pix] = best * isum;
}

// ---------------------------------------------------------------------------
extern "C" void kernel_launch(void* const* d_in, const int* in_sizes, int n_in,
                              void* d_out, int out_size)
{
    const float* feat0 = (const float*)d_in[0];
    const float* feat1 = (const float*)d_in[1];
    const float* feat2 = (const float*)d_in[2];
    const float* proj  = (const float*)d_in[3];
    const float* dvals = (const float*)d_in[4];
    const float* wreg  = (const float*)d_in[5];
    float* out = (float*)d_out;

    cudaFuncSetAttribute(warp_var_kernel,
                         cudaFuncAttributeMaxDynamicSharedMemorySize, SMEM_BYTES);

    prep_kernel<<<1, 1>>>(proj);
    transpose_kernel<<<dim3(HW/32, 3), dim3(32, 8)>>>(feat0, feat1, feat2);
    warp_var_kernel<<<DD*HH, 256, SMEM_BYTES>>>(dvals, wreg);
    sum_kernel<<<(DD*HH*WW)/256, 256>>>();
    depth_kernel<<<(HW + 127)/128, 128>>>(dvals, out);
}